// round 1
// baseline (speedup 1.0000x reference)
#include <cuda_runtime.h>
#include <cstdint>

#define IN_F   2048
#define OUT_F  2048
#define M_TOT  16384          // B*S = 8*2048
#define BM 128
#define BN 128
#define BK 32
#define PITCH 36              // 36 floats/row: 4r+c bank pattern -> conflict-free frag loads
#define KT (IN_F / BK)        // 64
#define SMEM_FLOATS (4 * BM * PITCH)   // double-buffered A + B
#define SMEM_BYTES  (SMEM_FLOATS * 4)  // 73728 B

// 16 MB scratch for W_eff (tf32-rounded). __device__ global: allocation-free.
__device__ float g_weff[(size_t)OUT_F * IN_F];

__device__ __forceinline__ uint32_t f2tf32(float x) {
    uint32_t r;
    asm("cvt.rna.tf32.f32 %0, %1;" : "=r"(r) : "f"(x));
    return r;
}

__device__ __forceinline__ void mma_tf32(float c[4], const uint32_t a[4], const uint32_t b[2]) {
    asm volatile(
        "mma.sync.aligned.m16n8k8.row.col.f32.tf32.tf32.f32 "
        "{%0,%1,%2,%3}, {%4,%5,%6,%7}, {%8,%9}, {%0,%1,%2,%3};\n"
        : "+f"(c[0]), "+f"(c[1]), "+f"(c[2]), "+f"(c[3])
        : "r"(a[0]), "r"(a[1]), "r"(a[2]), "r"(a[3]),
          "r"(b[0]), "r"(b[1]));
}

__device__ __forceinline__ void cp16(float* dst, const float* src) {
    uint32_t d = (uint32_t)__cvta_generic_to_shared(dst);
    asm volatile("cp.async.cg.shared.global [%0], [%1], 16;\n" :: "r"(d), "l"(src));
}

// ---------------------------------------------------------------------------
// Kernel 1: W_eff[o,i] = weight[o,i] + sum_r L0[r,o0,i0]*L1[r,o1,i1]*L2[r,o2,i2]
// (o0,o1,o2) = base-13 digits of o; same for i. Result pre-rounded to tf32 (rna).
// ---------------------------------------------------------------------------
__global__ void weff_kernel(const float* __restrict__ leaf,
                            const float* __restrict__ weight) {
    __shared__ float ls[2028];   // 3*4*13*13
    for (int t = threadIdx.x; t < 2028; t += blockDim.x) ls[t] = leaf[t];
    __syncthreads();
    int idx = blockIdx.x * blockDim.x + threadIdx.x;
    int o = idx >> 11;
    int i = idx & (IN_F - 1);
    int o0 = o / 169; int orm = o - o0 * 169; int o1 = orm / 13; int o2 = orm - o1 * 13;
    int i0 = i / 169; int irm = i - i0 * 169; int i1 = irm / 13; int i2 = irm - i1 * 13;
    float d = 0.f;
#pragma unroll
    for (int r = 0; r < 4; r++) {
        d += ls[r * 169 + o0 * 13 + i0]
           * ls[(4 + r) * 169 + o1 * 13 + i1]
           * ls[(8 + r) * 169 + o2 * 13 + i2];
    }
    float w = weight[idx] + d;
    g_weff[idx] = __uint_as_float(f2tf32(w));
}

// ---------------------------------------------------------------------------
// Kernel 2: y[m, n] = sum_k x[m,k] * W_eff[n,k] + bias[n]
// 128x128x32 CTA tile, 8 warps (2M x 4N), warp tile 64x32 as 4x4 m16n8k8 tf32.
// cp.async double buffer, one __syncthreads per K-iter.
// ---------------------------------------------------------------------------
__global__ void __launch_bounds__(256)
gemm_kernel(const float* __restrict__ x,
            const float* __restrict__ bias,
            float* __restrict__ y) {
    extern __shared__ float sm[];
    float* As = sm;                   // [2][BM][PITCH]
    float* Bs = sm + 2 * BM * PITCH;  // [2][BN][PITCH]

    const int tid  = threadIdx.x;
    const int lane = tid & 31;
    const int warp = tid >> 5;
    const int wm = warp >> 2;     // 0..1
    const int wn = warp & 3;      // 0..3
    const int mBase = blockIdx.y * BM;
    const int nBase = blockIdx.x * BN;

    const int lr = tid >> 3;          // 0..31 (row within 32-row slab)
    const int lc = (tid & 7) * 4;     // 0,4,...,28 (float4 column)

    const float* xg = x + (size_t)mBase * IN_F;
    const float* wg = g_weff + (size_t)nBase * IN_F;

    float c[4][4][4];
#pragma unroll
    for (int mt = 0; mt < 4; mt++)
#pragma unroll
        for (int nt = 0; nt < 4; nt++)
#pragma unroll
            for (int q = 0; q < 4; q++) c[mt][nt][q] = 0.f;

    // prefetch tile 0
    {
#pragma unroll
        for (int j = 0; j < 4; j++) {
            int row = lr + j * 32;
            cp16(As + row * PITCH + lc, xg + (size_t)row * IN_F + lc);
            cp16(Bs + row * PITCH + lc, wg + (size_t)row * IN_F + lc);
        }
        asm volatile("cp.async.commit_group;\n");
    }

    for (int kt = 0; kt < KT; kt++) {
        asm volatile("cp.async.wait_group 0;\n");
        __syncthreads();
        if (kt + 1 < KT) {
            const int k0 = (kt + 1) * BK;
            float* a = As + ((kt + 1) & 1) * BM * PITCH;
            float* b = Bs + ((kt + 1) & 1) * BM * PITCH;
#pragma unroll
            for (int j = 0; j < 4; j++) {
                int row = lr + j * 32;
                cp16(a + row * PITCH + lc, xg + (size_t)row * IN_F + k0 + lc);
                cp16(b + row * PITCH + lc, wg + (size_t)row * IN_F + k0 + lc);
            }
            asm volatile("cp.async.commit_group;\n");
        }
        const float* a = As + (kt & 1) * BM * PITCH;
        const float* b = Bs + (kt & 1) * BM * PITCH;
#pragma unroll
        for (int ks = 0; ks < BK / 8; ks++) {
            uint32_t af[4][4];
            uint32_t bf[4][2];
#pragma unroll
            for (int mt = 0; mt < 4; mt++) {
                int r  = wm * 64 + mt * 16 + (lane >> 2);
                int cc = ks * 8 + (lane & 3);
                af[mt][0] = f2tf32(a[r * PITCH + cc]);
                af[mt][1] = f2tf32(a[(r + 8) * PITCH + cc]);
                af[mt][2] = f2tf32(a[r * PITCH + cc + 4]);
                af[mt][3] = f2tf32(a[(r + 8) * PITCH + cc + 4]);
            }
#pragma unroll
            for (int nt = 0; nt < 4; nt++) {
                int n  = wn * 32 + nt * 8 + (lane >> 2);
                int kk = ks * 8 + (lane & 3);
                bf[nt][0] = __float_as_uint(b[n * PITCH + kk]);      // pre-rounded tf32
                bf[nt][1] = __float_as_uint(b[n * PITCH + kk + 4]);
            }
#pragma unroll
            for (int mt = 0; mt < 4; mt++)
#pragma unroll
                for (int nt = 0; nt < 4; nt++)
                    mma_tf32(c[mt][nt], af[mt], bf[nt]);
        }
        // single barrier per iter is safe: next iter's top barrier orders
        // everyone past compute(kt) before anyone cp.asyncs into buf[kt&1].
    }

    // epilogue: + bias, fp32 stores (32B sector-aligned float2 per fragment pair)
    float2 bb[4];
#pragma unroll
    for (int nt = 0; nt < 4; nt++) {
        int col = nBase + wn * 32 + nt * 8 + 2 * (lane & 3);
        bb[nt] = *(const float2*)(bias + col);
    }
    float* yg = y + (size_t)mBase * OUT_F + nBase;
#pragma unroll
    for (int mt = 0; mt < 4; mt++) {
        int r0 = wm * 64 + mt * 16 + (lane >> 2);
#pragma unroll
        for (int nt = 0; nt < 4; nt++) {
            int col = wn * 32 + nt * 8 + 2 * (lane & 3);
            float2 v0 = make_float2(c[mt][nt][0] + bb[nt].x, c[mt][nt][1] + bb[nt].y);
            float2 v1 = make_float2(c[mt][nt][2] + bb[nt].x, c[mt][nt][3] + bb[nt].y);
            *(float2*)(yg + (size_t)r0 * OUT_F + col) = v0;
            *(float2*)(yg + (size_t)(r0 + 8) * OUT_F + col) = v1;
        }
    }
}

extern "C" void kernel_launch(void* const* d_in, const int* in_sizes, int n_in,
                              void* d_out, int out_size) {
    // Robust input identification by element count (all four are distinct).
    const float *x = nullptr, *leaf = nullptr, *weight = nullptr, *bias = nullptr;
    for (int i = 0; i < n_in; i++) {
        switch (in_sizes[i]) {
            case M_TOT * IN_F:          x      = (const float*)d_in[i]; break; // 33554432
            case 3 * 4 * 13 * 13:       leaf   = (const float*)d_in[i]; break; // 2028
            case OUT_F * IN_F:          weight = (const float*)d_in[i]; break; // 4194304
            case OUT_F:                 bias   = (const float*)d_in[i]; break; // 2048
            default: break;
        }
    }
    float* y = (float*)d_out;

    weff_kernel<<<(OUT_F * IN_F) / 256, 256>>>(leaf, weight);

    cudaFuncSetAttribute(gemm_kernel, cudaFuncAttributeMaxDynamicSharedMemorySize, SMEM_BYTES);
    dim3 grid(OUT_F / BN, M_TOT / BM);   // (16, 128): N-inner raster -> A-panel L2 reuse
    gemm_kernel<<<grid, 256, SMEM_BYTES>>>(x, bias, y);
}

// round 3
// speedup vs baseline: 1.3502x; 1.3502x over previous
#include <cuda_runtime.h>
#include <cstdint>

#define IN_F   2048
#define OUT_F  2048
#define M_TOT  16384
#define BM 128
#define BN 128
#define BK 32
#define KT (IN_F / BK)            // 64
#define STAGES 3
#define A_STAGE_BYTES (BM * BK * 4)   // 16384
#define B_STAGE_BYTES (BN * BK * 4)   // 16384
#define STAGE_BYTES   (A_STAGE_BYTES + B_STAGE_BYTES)  // 32768
#define SMEM_BYTES    (STAGES * STAGE_BYTES)           // 98304

// Device-global scratch (allocation-free): fragment-permuted, tf32-rounded.
__device__ float  g_xperm[(size_t)M_TOT * IN_F];       // 134 MB
__device__ float2 g_wperm[((size_t)OUT_F * IN_F) / 2]; // 16 MB

__device__ __forceinline__ uint32_t f2tf32(float x) {
    uint32_t r; asm("cvt.rna.tf32.f32 %0, %1;" : "=r"(r) : "f"(x)); return r;
}

__device__ __forceinline__ void mma_tf32(float c[4], const uint32_t a[4], const uint32_t b[2]) {
    asm volatile(
        "mma.sync.aligned.m16n8k8.row.col.f32.tf32.tf32.f32 "
        "{%0,%1,%2,%3}, {%4,%5,%6,%7}, {%8,%9}, {%0,%1,%2,%3};\n"
        : "+f"(c[0]), "+f"(c[1]), "+f"(c[2]), "+f"(c[3])
        : "r"(a[0]), "r"(a[1]), "r"(a[2]), "r"(a[3]),
          "r"(b[0]), "r"(b[1]));
}

__device__ __forceinline__ void cp16(uint32_t dst, const void* src) {
    asm volatile("cp.async.cg.shared.global [%0], [%1], 16;\n" :: "r"(dst), "l"(src));
}
__device__ __forceinline__ uint32_t smem_u32(const void* p) {
    uint32_t a;
    asm("{ .reg .u64 t; cvta.to.shared.u64 t, %1; cvt.u32.u64 %0, t; }" : "=r"(a) : "l"(p));
    return a;
}

// ---------------------------------------------------------------------------
// Kernel A: permute + pre-round x into fragment order.
// Entry e (float4): lane=e&31; ks=(e>>5)&3; mt=(e>>7)&3; wm=(e>>9)&1;
//                   kc=(e>>10)&63; mBlk=e>>16.
// Values: (r,c), (r+8,c), (r,c+4), (r+8,c+4) with
//   r = mBlk*128 + wm*64 + mt*16 + (lane>>2);  c = kc*32 + ks*8 + (lane&3).
// ---------------------------------------------------------------------------
__global__ void __launch_bounds__(256)
xperm_kernel(const float* __restrict__ x) {
    const uint32_t e = blockIdx.x * 256 + threadIdx.x;     // 8,388,608 entries
    const int lane = e & 31;
    const int ks   = (e >> 5) & 3;
    const int mt   = (e >> 7) & 3;
    const int wm   = (e >> 9) & 1;
    const int kc   = (e >> 10) & 63;
    const int mBlk = e >> 16;
    const int r = mBlk * 128 + wm * 64 + mt * 16 + (lane >> 2);
    const int c = kc * 32 + ks * 8 + (lane & 3);
    const float* p0 = x + (size_t)r * IN_F + c;
    const float* p1 = p0 + 8 * IN_F;
    uint4 v;
    v.x = f2tf32(p0[0]);
    v.y = f2tf32(p1[0]);
    v.z = f2tf32(p0[4]);
    v.w = f2tf32(p1[4]);
    ((uint4*)g_xperm)[e] = v;
}

// ---------------------------------------------------------------------------
// Kernel B: W_eff = weight + kron-sum(leaf), tf32-rounded, fragment order.
// Entry e (float2): lane=e&31; ks=(e>>5)&3; nt=(e>>7)&3; wn=(e>>9)&3;
//                   kc=(e>>11)&63; nBlk=e>>17.
// Values: (o,i), (o,i+4) with o = nBlk*128 + wn*32 + nt*8 + (lane>>2),
//                             i = kc*32 + ks*8 + (lane&3).
// ---------------------------------------------------------------------------
__global__ void __launch_bounds__(256)
weff_kernel(const float* __restrict__ leaf, const float* __restrict__ weight) {
    __shared__ float ls[2028];
    for (int t = threadIdx.x; t < 2028; t += blockDim.x) ls[t] = leaf[t];
    __syncthreads();
    const uint32_t e = blockIdx.x * 256 + threadIdx.x;     // 2,097,152 entries
    const int lane = e & 31;
    const int ks   = (e >> 5) & 3;
    const int nt   = (e >> 7) & 3;
    const int wn   = (e >> 9) & 3;
    const int kc   = (e >> 11) & 63;
    const int nBlk = e >> 17;
    const int o = nBlk * 128 + wn * 32 + nt * 8 + (lane >> 2);
    const int i = kc * 32 + ks * 8 + (lane & 3);

    const int o0 = o / 169, orm = o - o0 * 169, o1 = orm / 13, o2 = orm - o1 * 13;
    float d0 = 0.f, d1 = 0.f;
#pragma unroll
    for (int half = 0; half < 2; half++) {
        int ii = i + half * 4;
        int i0 = ii / 169, irm = ii - i0 * 169, i1 = irm / 13, i2 = irm - i1 * 13;
        float d = 0.f;
#pragma unroll
        for (int rr = 0; rr < 4; rr++) {
            d += ls[rr * 169 + o0 * 13 + i0]
               * ls[(4 + rr) * 169 + o1 * 13 + i1]
               * ls[(8 + rr) * 169 + o2 * 13 + i2];
        }
        if (half == 0) d0 = d; else d1 = d;
    }
    const float* wrow = weight + (size_t)o * IN_F;
    float2 out;
    out.x = __uint_as_float(f2tf32(wrow[i] + d0));
    out.y = __uint_as_float(f2tf32(wrow[i + 4] + d1));
    g_wperm[e] = out;
}

// ---------------------------------------------------------------------------
// Kernel C: GEMM. Fragments stream straight from smem: A = LDS.128, B = LDS.64,
// zero CVT in the loop. 3-stage linear cp.async ring, one barrier per K-chunk.
// ---------------------------------------------------------------------------
__global__ void __launch_bounds__(256)
gemm_kernel(const float* __restrict__ bias, float* __restrict__ y) {
    extern __shared__ char smem[];
    const uint32_t sb = smem_u32(smem);

    const int tid  = threadIdx.x;
    const int lane = tid & 31;
    const int warp = tid >> 5;
    const int wm = warp >> 2;        // 0..1
    const int wn = warp & 3;         // 0..3
    const int nBlk = blockIdx.x;     // 0..15
    const int mBlk = blockIdx.y;     // 0..127

    const float*  ag = g_xperm + ((size_t)mBlk * 64) * (BM * BK);   // per-kc 4096 floats
    const float2* bg = g_wperm + ((size_t)nBlk * 64) * (BN * BK / 2);

    float c[4][4][4];
#pragma unroll
    for (int mt = 0; mt < 4; mt++)
#pragma unroll
        for (int nt = 0; nt < 4; nt++)
#pragma unroll
            for (int q = 0; q < 4; q++) c[mt][nt][q] = 0.f;

    auto load_stage = [&](int s, int kc) {
        uint32_t aB = sb + s * STAGE_BYTES;
        uint32_t bB = aB + A_STAGE_BYTES;
        const char* asrc = (const char*)(ag + (size_t)kc * (BM * BK));
        const char* bsrc = (const char*)(bg + (size_t)kc * (BN * BK / 2));
#pragma unroll
        for (int j = 0; j < 4; j++) {
            int off = (tid + j * 256) * 16;
            cp16(aB + off, asrc + off);
            cp16(bB + off, bsrc + off);
        }
        asm volatile("cp.async.commit_group;\n" ::: "memory");
    };

    load_stage(0, 0);
    load_stage(1, 1);

    for (int kt = 0; kt < KT; kt++) {
        if (kt + 2 < KT) asm volatile("cp.async.wait_group 1;\n" ::: "memory");
        else             asm volatile("cp.async.wait_group 0;\n" ::: "memory");
        __syncthreads();

        if (kt + 2 < KT) load_stage((kt + 2) % STAGES, kt + 2);

        const int s = kt % STAGES;
        const uint32_t aW = sb + s * STAGE_BYTES + wm * 8192 + lane * 16;
        const uint32_t bW = sb + s * STAGE_BYTES + A_STAGE_BYTES + wn * 4096 + lane * 8;
#pragma unroll
        for (int ks = 0; ks < 4; ks++) {
            uint32_t af[4][4];
            uint32_t bf[4][2];
#pragma unroll
            for (int mt = 0; mt < 4; mt++) {
                asm volatile("ld.shared.v4.b32 {%0,%1,%2,%3}, [%4];"
                    : "=r"(af[mt][0]), "=r"(af[mt][1]), "=r"(af[mt][2]), "=r"(af[mt][3])
                    : "r"(aW + (mt * 4 + ks) * 512));
            }
#pragma unroll
            for (int nt = 0; nt < 4; nt++) {
                asm volatile("ld.shared.v2.b32 {%0,%1}, [%2];"
                    : "=r"(bf[nt][0]), "=r"(bf[nt][1])
                    : "r"(bW + (nt * 4 + ks) * 256));
            }
#pragma unroll
            for (int mt = 0; mt < 4; mt++)
#pragma unroll
                for (int nt = 0; nt < 4; nt++)
                    mma_tf32(c[mt][nt], af[mt], bf[nt]);
        }
    }

    // Epilogue: + bias, float2 stores.
    const int mBase = mBlk * BM, nBase = nBlk * BN;
    float2 bb[4];
#pragma unroll
    for (int nt = 0; nt < 4; nt++) {
        int col = nBase + wn * 32 + nt * 8 + 2 * (lane & 3);
        bb[nt] = *(const float2*)(bias + col);
    }
    float* yg = y + (size_t)mBase * OUT_F + nBase;
#pragma unroll
    for (int mt = 0; mt < 4; mt++) {
        int r0 = wm * 64 + mt * 16 + (lane >> 2);
#pragma unroll
        for (int nt = 0; nt < 4; nt++) {
            int col = wn * 32 + nt * 8 + 2 * (lane & 3);
            float2 v0 = make_float2(c[mt][nt][0] + bb[nt].x, c[mt][nt][1] + bb[nt].y);
            float2 v1 = make_float2(c[mt][nt][2] + bb[nt].x, c[mt][nt][3] + bb[nt].y);
            *(float2*)(yg + (size_t)r0 * OUT_F + col) = v0;
            *(float2*)(yg + (size_t)(r0 + 8) * OUT_F + col) = v1;
        }
    }
}

extern "C" void kernel_launch(void* const* d_in, const int* in_sizes, int n_in,
                              void* d_out, int out_size) {
    const float *x = nullptr, *leaf = nullptr, *weight = nullptr, *bias = nullptr;
    for (int i = 0; i < n_in; i++) {
        switch (in_sizes[i]) {
            case M_TOT * IN_F:    x      = (const float*)d_in[i]; break;
            case 3 * 4 * 13 * 13: leaf   = (const float*)d_in[i]; break;
            case OUT_F * IN_F:    weight = (const float*)d_in[i]; break;
            case OUT_F:           bias   = (const float*)d_in[i]; break;
            default: break;
        }
    }
    float* y = (float*)d_out;

    xperm_kernel<<<(M_TOT * IN_F / 4) / 256, 256>>>(x);
    weff_kernel<<<(OUT_F * IN_F / 2) / 256, 256>>>(leaf, weight);

    static int smem_set = 0;
    if (!smem_set) {
        cudaFuncSetAttribute(gemm_kernel, cudaFuncAttributeMaxDynamicSharedMemorySize, SMEM_BYTES);
        smem_set = 1;
    }
    dim3 grid(OUT_F / BN, M_TOT / BM);   // (16, 128): N-inner raster, W stays in L2
    gemm_kernel<<<grid, 256, SMEM_BYTES>>>(bias, y);
}